// round 4
// baseline (speedup 1.0000x reference)
#include <cuda_runtime.h>
#include <cstdint>

// ============================================================================
// IntraSentenceAttention, flash-style, both GEMMs on mma.sync tf32.
//   S = Xi·Xjᵀ   (m16n8k8 tf32, k = d)
//   P = exp(S + min(i-j,10)) · mj      (register epilogue, P -> SMEM as tf32)
//   O += P·Xj    (m16n8k8 tf32, k = j)
// B=32, T=1024, D=128. CTA: 128 i-rows, 16 j-tiles of 64. 512 thr / 16 warps.
// Double-buffered Xj staging; pair-scoped named barriers for the P handoff.
// ============================================================================

namespace {
constexpr int Bb = 32, Tt = 1024, Dd = 128;
constexpr int TM = 128, TN = 64;
constexpr int NJT = Tt / TN;            // 16
constexpr float EPSF = 1e-7f;

constexpr int XIP = 132;                // pitches chosen so bank = 4*qrow+qk (conflict-free)
constexpr int XJP = 132;
constexpr int PPITCH = 68;

// SMEM float offsets
constexpr int O_XI  = 0;                          // 128*132
constexpr int O_XJ0 = O_XI + TM * XIP;            // 64*132
constexpr int O_XJ1 = O_XJ0 + TN * XJP;           // 64*132
constexpr int O_P   = O_XJ1 + TN * XJP;           // 128*68
constexpr int O_MI  = O_P + TM * PPITCH;          // 128
constexpr int O_MJ0 = O_MI + TM;                  // 64
constexpr int O_MJ1 = O_MJ0 + TN;                 // 64
constexpr int O_RP  = O_MJ1 + TN;                 // 2*128
constexpr int O_INV = O_RP + 2 * TM;              // 128
constexpr int SMEM_FLOATS = O_INV + TM;
constexpr int SMEM_BYTES = SMEM_FLOATS * 4;       // ~169 KB
}

__device__ int g_mask_mode;  // 0 = bool bytes, 1 = int32, 2 = float32

__global__ void detect_mask_kernel(const unsigned int* __restrict__ w, int nwords) {
    __shared__ int f01[2];
    if (threadIdx.x < 2) f01[threadIdx.x] = 0;
    __syncthreads();
    int not_int = 0, not_flt = 0;
    for (int i = threadIdx.x; i < nwords; i += blockDim.x) {
        unsigned v = w[i];
        if (v > 1u) not_int = 1;
        if (v != 0u && v != 0x3F800000u) not_flt = 1;
    }
    if (not_int) atomicOr(&f01[0], 1);
    if (not_flt) atomicOr(&f01[1], 1);
    __syncthreads();
    if (threadIdx.x == 0) g_mask_mode = (!f01[0]) ? 1 : ((!f01[1]) ? 2 : 0);
}

__device__ __forceinline__ float get_mask(const void* m, int idx, int mode) {
    if (mode == 1) return ((const int*)m)[idx] ? 1.0f : 0.0f;
    if (mode == 2) return ((const float*)m)[idx];
    return ((const unsigned char*)m)[idx] ? 1.0f : 0.0f;
}

__device__ __forceinline__ uint32_t rna_tf32_bits(float x) {
    uint32_t u;
    asm("cvt.rna.tf32.f32 %0, %1;" : "=r"(u) : "f"(x));
    return u;
}
__device__ __forceinline__ float rna_tf32(float x) { return __uint_as_float(rna_tf32_bits(x)); }
__device__ __forceinline__ float4 rna4(float4 v) {
    v.x = rna_tf32(v.x); v.y = rna_tf32(v.y);
    v.z = rna_tf32(v.z); v.w = rna_tf32(v.w);
    return v;
}

__device__ __forceinline__ void mma_tf32(float d[4], uint32_t a0, uint32_t a1,
                                         uint32_t a2, uint32_t a3,
                                         uint32_t b0, uint32_t b1) {
    asm volatile(
        "mma.sync.aligned.m16n8k8.row.col.f32.tf32.tf32.f32 "
        "{%0,%1,%2,%3}, {%4,%5,%6,%7}, {%8,%9}, {%0,%1,%2,%3};"
        : "+f"(d[0]), "+f"(d[1]), "+f"(d[2]), "+f"(d[3])
        : "r"(a0), "r"(a1), "r"(a2), "r"(a3), "r"(b0), "r"(b1));
}

#define PAIR_BAR(id) asm volatile("bar.sync %0, 64;" :: "r"(id) : "memory")

__global__ __launch_bounds__(512, 1)
void attn_mma(const float* __restrict__ x, const void* __restrict__ mask,
              float* __restrict__ out) {
    extern __shared__ float smem[];
    float* sXi  = smem + O_XI;
    float* sP   = smem + O_P;
    float* sMi  = smem + O_MI;
    float* sRP  = smem + O_RP;
    float* sInv = smem + O_INV;
    const uint32_t* uXi = (const uint32_t*)sXi;
    const uint32_t* uP  = (const uint32_t*)sP;

    const int tid  = threadIdx.x;
    const int w    = tid >> 5, lane = tid & 31;
    const int band = w >> 1;          // 0..7 : 16-row m-band
    const int half = w & 1;           // A: j-half (32 cols); B: d-half (64 cols)
    const int qrow = lane >> 2;       // 0..7
    const int qk   = lane & 3;        // 0..3
    const int arow0 = band * 16;

    const int b  = blockIdx.y;
    const int i0 = blockIdx.x * TM;
    const int mode = g_mask_mode;
    const float* xb = x + (size_t)b * Tt * Dd;

    // ---- stage persistent Xi tile (rna-rounded), row masks, Xj tile 0 ----
    for (int e = tid; e < TM * 32; e += 512) {
        int r = e >> 5, c4 = (e & 31) << 2;
        *(float4*)(sXi + r * XIP + c4) = rna4(*(const float4*)(xb + (size_t)(i0 + r) * Dd + c4));
    }
    for (int e = tid; e < TN * 32; e += 512) {
        int r = e >> 5, c4 = (e & 31) << 2;
        *(float4*)(smem + O_XJ0 + r * XJP + c4) = rna4(*(const float4*)(xb + (size_t)r * Dd + c4));
    }
    if (tid < TM) sMi[tid] = get_mask(mask, b * Tt + i0 + tid, mode);
    if (tid < TN) smem[O_MJ0 + tid] = get_mask(mask, b * Tt + tid, mode);
    __syncthreads();

    float acc[8][4];
    #pragma unroll
    for (int nf = 0; nf < 8; nf++)
        #pragma unroll
        for (int c = 0; c < 4; c++) acc[nf][c] = 0.0f;
    float rsum[2] = {0.f, 0.f};

    // staging split: 2048 float4 over 512 threads = 4 each
    const int st_r  = tid >> 3;           // row 0..63  (tid/8)
    const int st_c4 = (tid & 7) << 2;     // float4 col {0..7}*4 -> +8 stride covers 32

    for (int jt = 0; jt < NJT; ++jt) {
        const int j0 = jt * TN;
        const int cur = jt & 1;
        const float* sXj = smem + (cur ? O_XJ1 : O_XJ0);
        const float* sMj = smem + (cur ? O_MJ1 : O_MJ0);
        const uint32_t* uXj = (const uint32_t*)sXj;

        // ---- issue global prefetch of tile jt+1 into registers (hidden by MMA) ----
        float4 pf[4];
        float mjpf = 0.f;
        if (jt + 1 < NJT) {
            const float* src = xb + (size_t)(j0 + TN) * Dd;
            #pragma unroll
            for (int i = 0; i < 4; i++)
                pf[i] = *(const float4*)(src + (size_t)st_r * Dd + st_c4 + 32 * i);
            if (tid < TN) mjpf = get_mask(mask, b * Tt + j0 + TN + tid, mode);
        }

        // ================= phase A: S(16x32 per warp) = Xi · Xjᵀ =================
        float s[4][4];
        #pragma unroll
        for (int nf = 0; nf < 4; nf++)
            #pragma unroll
            for (int c = 0; c < 4; c++) s[nf][c] = 0.0f;

        #pragma unroll
        for (int ks = 0; ks < Dd / 8; ++ks) {
            const int k0 = ks * 8;
            const uint32_t* pa = uXi + (arow0 + qrow) * XIP + k0 + qk;
            uint32_t a0 = pa[0], a1 = pa[8 * XIP], a2 = pa[4], a3 = pa[8 * XIP + 4];
            #pragma unroll
            for (int nf = 0; nf < 4; nf++) {
                const uint32_t* pb = uXj + (half * 32 + nf * 8 + qrow) * XJP + k0 + qk;
                mma_tf32(s[nf], a0, a1, a2, a3, pb[0], pb[4]);
            }
        }

        // ---- wait for pair's phase B of previous tile to finish reading P ----
        PAIR_BAR(1 + band);

        // ---- epilogue: P = exp(S + dist) * mj, rowsum, store P (tf32) ----
        {
            const int rl0 = arow0 + qrow;
            const int ig0 = i0 + rl0;
            #pragma unroll
            for (int nf = 0; nf < 4; nf++) {
                const int jl = half * 32 + nf * 8 + 2 * qk;
                const int jg = j0 + jl;
                const float mj0 = sMj[jl], mj1 = sMj[jl + 1];
                float p0 = __expf(s[nf][0] + fminf((float)(ig0 - jg), 10.f)) * mj0;
                float p1 = __expf(s[nf][1] + fminf((float)(ig0 - jg - 1), 10.f)) * mj1;
                float p2 = __expf(s[nf][2] + fminf((float)(ig0 + 8 - jg), 10.f)) * mj0;
                float p3 = __expf(s[nf][3] + fminf((float)(ig0 + 8 - jg - 1), 10.f)) * mj1;
                rsum[0] += p0 + p1;
                rsum[1] += p2 + p3;
                *(uint2*)(sP + rl0 * PPITCH + jl) =
                    make_uint2(rna_tf32_bits(p0), rna_tf32_bits(p1));
                *(uint2*)(sP + (rl0 + 8) * PPITCH + jl) =
                    make_uint2(rna_tf32_bits(p2), rna_tf32_bits(p3));
            }
        }
        PAIR_BAR(1 + band);   // P visible to the pair

        // ================= phase B: O(16x64 per warp) += P · Xj =================
        #pragma unroll
        for (int ks = 0; ks < TN / 8; ++ks) {
            const int k0 = ks * 8;
            const uint32_t* pa = uP + (arow0 + qrow) * PPITCH + k0 + qk;
            uint32_t a0 = pa[0], a1 = pa[8 * PPITCH], a2 = pa[4], a3 = pa[8 * PPITCH + 4];
            #pragma unroll
            for (int nf = 0; nf < 8; nf++) {
                const uint32_t* pb = uXj + (k0 + qk) * XJP + half * 64 + nf * 8 + qrow;
                mma_tf32(acc[nf], a0, a1, a2, a3, pb[0], pb[4 * XJP]);
            }
        }

        // ---- store prefetched tile jt+1 into the other buffer ----
        if (jt + 1 < NJT) {
            float* dXj = smem + (cur ? O_XJ0 : O_XJ1);
            #pragma unroll
            for (int i = 0; i < 4; i++)
                *(float4*)(dXj + st_r * XJP + st_c4 + 32 * i) = rna4(pf[i]);
            if (tid < TN) smem[(cur ? O_MJ0 : O_MJ1) + tid] = mjpf;
        }
        __syncthreads();
    }

    // ---- row-sum reduction across qk lanes, then across the two j-halves ----
    #pragma unroll
    for (int rh = 0; rh < 2; rh++) {
        float v = rsum[rh];
        v += __shfl_xor_sync(0xffffffffu, v, 1);
        v += __shfl_xor_sync(0xffffffffu, v, 2);
        if (qk == 0) sRP[half * TM + arow0 + rh * 8 + qrow] = v;
    }
    __syncthreads();
    if (tid < TM) sInv[tid] = sMi[tid] / (sRP[tid] + sRP[TM + tid] + EPSF);
    __syncthreads();

    // ---- write O ----
    {
        const int rl0 = arow0 + qrow;
        const float inv0 = sInv[rl0], inv1 = sInv[rl0 + 8];
        float* o0 = out + ((size_t)b * Tt + i0 + rl0) * Dd;
        float* o1 = o0 + 8 * Dd;
        #pragma unroll
        for (int nf = 0; nf < 8; nf++) {
            const int cl = half * 64 + nf * 8 + 2 * qk;
            *(float2*)(o0 + cl) = make_float2(acc[nf][0] * inv0, acc[nf][1] * inv0);
            *(float2*)(o1 + cl) = make_float2(acc[nf][2] * inv1, acc[nf][3] * inv1);
        }
    }
}

extern "C" void kernel_launch(void* const* d_in, const int* in_sizes, int n_in,
                              void* d_out, int out_size) {
    const float* x   = (const float*)d_in[0];
    const void* mask = d_in[1];
    float* out       = (float*)d_out;

    cudaFuncSetAttribute(attn_mma, cudaFuncAttributeMaxDynamicSharedMemorySize, SMEM_BYTES);

    detect_mask_kernel<<<1, 256>>>((const unsigned int*)mask, (Bb * Tt) / 4);
    dim3 grid(Tt / TM, Bb);
    attn_mma<<<grid, 512, SMEM_BYTES>>>(x, mask, out);
}

// round 5
// speedup vs baseline: 2.1257x; 2.1257x over previous
#include <cuda_runtime.h>
#include <cuda_fp16.h>
#include <cstdint>

// ============================================================================
// IntraSentenceAttention, flash-style, fp16 mma.sync m16n8k16 + ldmatrix.
//   S = Xi·Xjᵀ   (A=Xi fp16 ldmatrix, B=Xj fp16 ldmatrix non-trans; k = d)
//   P = exp(S + min(i-j,10)) · mj   (fp32 epilogue; P -> SMEM as fp16)
//   O += P·Xj    (A=P fp16 ldmatrix, B=Xj fp16 ldmatrix TRANS; k = j)
// B=32, T=1024, D=128. CTA 128 i-rows, 16 j-tiles of 64, 256 thr / 8 warps.
// x pre-converted to fp16 in a prepass; tiles staged with cp.async (2-deep).
// ============================================================================

namespace {
constexpr int Bb = 32, Tt = 1024, Dd = 128;
constexpr int TM = 128, TN = 64;
constexpr int NJT = Tt / TN;             // 16
constexpr float EPSF = 1e-7f;

constexpr int PX = 272;                  // Xi/Xj row pitch bytes (128 fp16 + pad), ≡16 mod 128
constexpr int PP = 144;                  // P row pitch bytes (64 fp16 + pad),  ≡16 mod 128

// SMEM byte offsets
constexpr int SM_XI  = 0;                        // 128*272 = 34816
constexpr int SM_XJ0 = 34816;                    // 64*272  = 17408
constexpr int SM_XJ1 = 52224;                    // 17408
constexpr int SM_P   = 69632;                    // 128*144 = 18432
constexpr int SM_MI  = 88064;                    // 128 f
constexpr int SM_MJ0 = 88576;                    // 64 f
constexpr int SM_MJ1 = 88832;                    // 64 f
constexpr int SM_RP  = 89088;                    // 256 f
constexpr int SM_INV = 90112;                    // 128 f
constexpr int SMEM_BYTES = 90624;
}

__device__ uint2 g_x16[Bb * Tt * Dd / 4];   // x as fp16, [b][t][d] row-major
__device__ int   g_mask_mode;               // 0 = bool bytes, 1 = int32, 2 = float32

// ---------------------------------------------------------------- helpers
__global__ void detect_mask_kernel(const unsigned int* __restrict__ w, int nwords) {
    __shared__ int f01[2];
    if (threadIdx.x < 2) f01[threadIdx.x] = 0;
    __syncthreads();
    int not_int = 0, not_flt = 0;
    for (int i = threadIdx.x; i < nwords; i += blockDim.x) {
        unsigned v = w[i];
        if (v > 1u) not_int = 1;
        if (v != 0u && v != 0x3F800000u) not_flt = 1;
    }
    if (not_int) atomicOr(&f01[0], 1);
    if (not_flt) atomicOr(&f01[1], 1);
    __syncthreads();
    if (threadIdx.x == 0) g_mask_mode = (!f01[0]) ? 1 : ((!f01[1]) ? 2 : 0);
}

__device__ __forceinline__ float get_mask(const void* m, int idx, int mode) {
    if (mode == 1) return ((const int*)m)[idx] ? 1.0f : 0.0f;
    if (mode == 2) return ((const float*)m)[idx];
    return ((const unsigned char*)m)[idx] ? 1.0f : 0.0f;
}

__global__ void cvt16_kernel(const float4* __restrict__ x) {
    int i = blockIdx.x * 256 + threadIdx.x;
    float4 v = x[i];
    __half2 h0 = __floats2half2_rn(v.x, v.y);
    __half2 h1 = __floats2half2_rn(v.z, v.w);
    g_x16[i] = make_uint2(*(const uint32_t*)&h0, *(const uint32_t*)&h1);
}

__device__ __forceinline__ uint32_t smem_u32(const void* p) {
    uint32_t a;
    asm("{ .reg .u64 t; cvta.to.shared.u64 t, %1; cvt.u32.u64 %0, t; }" : "=r"(a) : "l"(p));
    return a;
}
__device__ __forceinline__ void cp16(uint32_t dst, const void* src) {
    asm volatile("cp.async.cg.shared.global [%0], [%1], 16;" :: "r"(dst), "l"(src));
}
#define CP_COMMIT() asm volatile("cp.async.commit_group;" ::: "memory")
#define CP_WAIT0()  asm volatile("cp.async.wait_group 0;" ::: "memory")

__device__ __forceinline__ void ldsm4(uint32_t r[4], uint32_t a) {
    asm volatile("ldmatrix.sync.aligned.m8n8.x4.shared.b16 {%0,%1,%2,%3}, [%4];"
                 : "=r"(r[0]), "=r"(r[1]), "=r"(r[2]), "=r"(r[3]) : "r"(a));
}
__device__ __forceinline__ void ldsm4t(uint32_t r[4], uint32_t a) {
    asm volatile("ldmatrix.sync.aligned.m8n8.x4.trans.shared.b16 {%0,%1,%2,%3}, [%4];"
                 : "=r"(r[0]), "=r"(r[1]), "=r"(r[2]), "=r"(r[3]) : "r"(a));
}
__device__ __forceinline__ void mma_f16(float d[4], const uint32_t a[4],
                                        uint32_t b0, uint32_t b1) {
    asm volatile(
        "mma.sync.aligned.m16n8k16.row.col.f32.f16.f16.f32 "
        "{%0,%1,%2,%3}, {%4,%5,%6,%7}, {%8,%9}, {%0,%1,%2,%3};"
        : "+f"(d[0]), "+f"(d[1]), "+f"(d[2]), "+f"(d[3])
        : "r"(a[0]), "r"(a[1]), "r"(a[2]), "r"(a[3]), "r"(b0), "r"(b1));
}

#define PAIR_BAR(id) asm volatile("bar.sync %0, 64;" :: "r"(id) : "memory")

// ---------------------------------------------------------------- main kernel
__global__ __launch_bounds__(256, 1)
void attn_mma(const void* __restrict__ mask, float* __restrict__ out) {
    extern __shared__ char sm[];
    const uint32_t sb = smem_u32(sm);

    const int tid  = threadIdx.x;
    const int w    = tid >> 5, lane = tid & 31;
    const int band = w >> 1;          // 0..3 : 32-row m-band
    const int half = w & 1;           // A: j-half (32); B: d-half (64)
    const int qrow = lane >> 2;       // 0..7
    const int qk   = lane & 3;        // 0..3
    const int arow0 = band * 32;

    const int b  = blockIdx.y;
    const int i0 = blockIdx.x * TM;
    const int mode = g_mask_mode;
    const char* gx = (const char*)g_x16;     // fp16 x, 256B per row

    // ldmatrix lane-address offsets (bytes, without ks / nb / buffer terms)
    const int l7 = lane & 7, l8 = (lane >> 3) & 1, l16 = (lane >> 4) & 1;
    const uint32_t offA_xi = (uint32_t)((arow0 + l7 + 8 * l8) * PX + l16 * 16);
    const uint32_t offB_A  = (uint32_t)((half * 32 + l7 + 8 * l16) * PX + l8 * 16);
    const uint32_t offA_P  = (uint32_t)((arow0 + l7 + 8 * l8) * PP + l16 * 16);
    const uint32_t offB_B  = (uint32_t)((l7 + 8 * l8) * PX + (half * 64 + 8 * l16) * 2);

    // ---- stage Xi (cp.async) + tile-0 Xj + masks ----
    {
        const int xr = tid >> 1;                          // 0..127
        const size_t srow = (size_t)(b * Tt + i0 + xr) * 256;
        #pragma unroll
        for (int i = 0; i < 8; i++) {
            const int ch = (tid & 1) + 2 * i;
            cp16(sb + SM_XI + xr * PX + ch * 16, gx + srow + ch * 16);
        }
        const int jr = tid >> 2;                          // 0..63
        const size_t jrow = (size_t)(b * Tt + jr) * 256;
        #pragma unroll
        for (int i = 0; i < 4; i++) {
            const int ch = (tid & 3) + 4 * i;
            cp16(sb + SM_XJ0 + jr * PX + ch * 16, gx + jrow + ch * 16);
        }
        CP_COMMIT();
    }
    if (tid < TM) ((float*)(sm + SM_MI))[tid] = get_mask(mask, b * Tt + i0 + tid, mode);
    if (tid < TN) ((float*)(sm + SM_MJ0))[tid] = get_mask(mask, b * Tt + tid, mode);

    float acc[2][8][4];
    #pragma unroll
    for (int mf = 0; mf < 2; mf++)
        #pragma unroll
        for (int nf = 0; nf < 8; nf++)
            #pragma unroll
            for (int c = 0; c < 4; c++) acc[mf][nf][c] = 0.0f;
    float rsum[2][2] = {{0.f, 0.f}, {0.f, 0.f}};

    for (int jt = 0; jt < NJT; ++jt) {
        const int j0 = jt * TN;
        const uint32_t xjb = sb + ((jt & 1) ? SM_XJ1 : SM_XJ0);
        const float* sMj = (const float*)(sm + ((jt & 1) ? SM_MJ1 : SM_MJ0));

        CP_WAIT0();
        __syncthreads();   // tile jt staged & visible; previous readers done

        // ---- issue cp.async for tile jt+1 into the other buffer ----
        if (jt + 1 < NJT) {
            const uint32_t dst = sb + (((jt + 1) & 1) ? SM_XJ1 : SM_XJ0);
            const int jr = tid >> 2;
            const size_t jrow = (size_t)(b * Tt + j0 + TN + jr) * 256;
            #pragma unroll
            for (int i = 0; i < 4; i++) {
                const int ch = (tid & 3) + 4 * i;
                cp16(dst + jr * PX + ch * 16, gx + jrow + ch * 16);
            }
            CP_COMMIT();
            if (tid < TN)
                ((float*)(sm + (((jt + 1) & 1) ? SM_MJ1 : SM_MJ0)))[tid] =
                    get_mask(mask, b * Tt + j0 + TN + tid, mode);
        }

        // ================= phase A: S(32x32 per warp) = Xi · Xjᵀ =================
        float s[2][4][4];
        #pragma unroll
        for (int mf = 0; mf < 2; mf++)
            #pragma unroll
            for (int nf = 0; nf < 4; nf++)
                #pragma unroll
                for (int c = 0; c < 4; c++) s[mf][nf][c] = 0.0f;

        #pragma unroll
        for (int ks = 0; ks < Dd / 16; ++ks) {
            uint32_t a[2][4];
            ldsm4(a[0], sb + SM_XI + offA_xi + ks * 32);
            ldsm4(a[1], sb + SM_XI + offA_xi + 16 * PX + ks * 32);
            #pragma unroll
            for (int nb = 0; nb < 2; nb++) {
                uint32_t bb[4];
                ldsm4(bb, xjb + offB_A + nb * 16 * PX + ks * 32);
                mma_f16(s[0][2 * nb],     a[0], bb[0], bb[1]);
                mma_f16(s[0][2 * nb + 1], a[0], bb[2], bb[3]);
                mma_f16(s[1][2 * nb],     a[1], bb[0], bb[1]);
                mma_f16(s[1][2 * nb + 1], a[1], bb[2], bb[3]);
            }
        }

        PAIR_BAR(1 + band);   // pair's phase B (prev tile) done reading P

        // ---- epilogue: P = exp(S + dist) * mj, rowsum, store P fp16 ----
        #pragma unroll
        for (int mf = 0; mf < 2; mf++) {
            const int rl0 = arow0 + mf * 16 + qrow;
            const int ig0 = i0 + rl0;
            #pragma unroll
            for (int nf = 0; nf < 4; nf++) {
                const int jl = half * 32 + nf * 8 + 2 * qk;
                const int jg = j0 + jl;
                const float mj0 = sMj[jl], mj1 = sMj[jl + 1];
                float p0 = __expf(s[mf][nf][0] + fminf((float)(ig0 - jg), 10.f)) * mj0;
                float p1 = __expf(s[mf][nf][1] + fminf((float)(ig0 - jg - 1), 10.f)) * mj1;
                float p2 = __expf(s[mf][nf][2] + fminf((float)(ig0 + 8 - jg), 10.f)) * mj0;
                float p3 = __expf(s[mf][nf][3] + fminf((float)(ig0 + 8 - jg - 1), 10.f)) * mj1;
                rsum[mf][0] += p0 + p1;
                rsum[mf][1] += p2 + p3;
                __half2 h01 = __floats2half2_rn(p0, p1);
                __half2 h23 = __floats2half2_rn(p2, p3);
                uint32_t* up = (uint32_t*)(sm + SM_P);
                const int ci = half * 16 + nf * 4 + qk;       // uint col index
                up[rl0 * 36 + ci]       = *(const uint32_t*)&h01;
                up[(rl0 + 8) * 36 + ci] = *(const uint32_t*)&h23;
            }
        }
        PAIR_BAR(1 + band);   // P visible to the pair

        // ================= phase B: O(32x64 per warp) += P · Xj =================
        #pragma unroll
        for (int ks = 0; ks < TN / 16; ++ks) {
            uint32_t a[2][4];
            ldsm4(a[0], sb + SM_P + offA_P + ks * 32);
            ldsm4(a[1], sb + SM_P + offA_P + 16 * PP + ks * 32);
            #pragma unroll
            for (int nb = 0; nb < 4; nb++) {
                uint32_t bb[4];
                ldsm4t(bb, xjb + offB_B + nb * 32 + ks * 16 * PX);
                mma_f16(acc[0][2 * nb],     a[0], bb[0], bb[1]);
                mma_f16(acc[0][2 * nb + 1], a[0], bb[2], bb[3]);
                mma_f16(acc[1][2 * nb],     a[1], bb[0], bb[1]);
                mma_f16(acc[1][2 * nb + 1], a[1], bb[2], bb[3]);
            }
        }
        __syncthreads();   // all reads of buf jt done before jt+1 issues into it
    }

    // ---- row-sum reduction + inverse ----
    float* sRP  = (float*)(sm + SM_RP);
    float* sInv = (float*)(sm + SM_INV);
    #pragma unroll
    for (int mf = 0; mf < 2; mf++)
        #pragma unroll
        for (int rh = 0; rh < 2; rh++) {
            float v = rsum[mf][rh];
            v += __shfl_xor_sync(0xffffffffu, v, 1);
            v += __shfl_xor_sync(0xffffffffu, v, 2);
            if (qk == 0) sRP[half * TM + arow0 + mf * 16 + rh * 8 + qrow] = v;
        }
    __syncthreads();
    if (tid < TM)
        sInv[tid] = ((float*)(sm + SM_MI))[tid] / (sRP[tid] + sRP[TM + tid] + EPSF);
    __syncthreads();

    // ---- write O ----
    #pragma unroll
    for (int mf = 0; mf < 2; mf++) {
        const int rl0 = arow0 + mf * 16 + qrow;
        const float inv0 = sInv[rl0], inv1 = sInv[rl0 + 8];
        float* o0 = out + ((size_t)b * Tt + i0 + rl0) * Dd;
        float* o1 = o0 + 8 * Dd;
        #pragma unroll
        for (int nf = 0; nf < 8; nf++) {
            const int cl = half * 64 + nf * 8 + 2 * qk;
            *(float2*)(o0 + cl) = make_float2(acc[mf][nf][0] * inv0, acc[mf][nf][1] * inv0);
            *(float2*)(o1 + cl) = make_float2(acc[mf][nf][2] * inv1, acc[mf][nf][3] * inv1);
        }
    }
}

extern "C" void kernel_launch(void* const* d_in, const int* in_sizes, int n_in,
                              void* d_out, int out_size) {
    const float* x   = (const float*)d_in[0];
    const void* mask = d_in[1];
    float* out       = (float*)d_out;

    cudaFuncSetAttribute(attn_mma, cudaFuncAttributeMaxDynamicSharedMemorySize, SMEM_BYTES);

    detect_mask_kernel<<<1, 256>>>((const unsigned int*)mask, (Bb * Tt) / 4);
    cvt16_kernel<<<(Bb * Tt * Dd / 4) / 256, 256>>>((const float4*)x);
    dim3 grid(Tt / TM, Bb);
    attn_mma<<<grid, 256, SMEM_BYTES>>>(mask, out);
}

// round 6
// speedup vs baseline: 2.6011x; 1.2236x over previous
#include <cuda_runtime.h>
#include <cuda_fp16.h>
#include <cstdint>

// ============================================================================
// IntraSentenceAttention, flash-style, fp16 mma.sync m16n8k16 + ldmatrix.
//   S = Xi·Xjᵀ   (A=Xi fp16 ldmatrix, B=Xj fp16 ldmatrix non-trans; k = d)
//   P = exp(S + min(i-j,10)) · mj   (fp32 epilogue; P -> SMEM as fp16)
//   O += P·Xj    (A=P fp16 ldmatrix, B=Xj fp16 ldmatrix TRANS; k = j)
// B=32, T=1024, D=128. CTA 128 i-rows, 16 j-tiles of 64, 256 thr / 8 warps,
// 2 CTAs/SM. Mask-dtype detection runs inside the fp16-convert prepass.
// ============================================================================

namespace {
constexpr int Bb = 32, Tt = 1024, Dd = 128;
constexpr int TM = 128, TN = 64;
constexpr int NJT = Tt / TN;             // 16
constexpr float EPSF = 1e-7f;

constexpr int PX = 272;                  // Xi/Xj row pitch bytes (128 fp16 + pad), ≡16 mod 128
constexpr int PP = 144;                  // P row pitch bytes (64 fp16 + pad),  ≡16 mod 128

// SMEM byte offsets
constexpr int SM_XI  = 0;                        // 128*272 = 34816
constexpr int SM_XJ0 = 34816;                    // 64*272  = 17408
constexpr int SM_XJ1 = 52224;                    // 17408
constexpr int SM_P   = 69632;                    // 128*144 = 18432
constexpr int SM_MI  = 88064;                    // 128 f
constexpr int SM_MJ0 = 88576;                    // 64 f
constexpr int SM_MJ1 = 88832;                    // 64 f
constexpr int SM_RP  = 89088;                    // 256 f
constexpr int SM_INV = 90112;                    // 128 f
constexpr int SMEM_BYTES = 90624;
}

__device__ uint2 g_x16[Bb * Tt * Dd / 4];   // x as fp16, [b][t][d] row-major
__device__ int   g_flags[2];                // [0]=not_int32, [1]=not_float32

__global__ void init_flags_kernel() {
    g_flags[0] = 0;
    g_flags[1] = 0;
}

// fp16 convert over all of x; blocks 0..63 additionally scan the mask words.
__global__ void cvt16_detect_kernel(const float4* __restrict__ x,
                                    const unsigned int* __restrict__ mw) {
    int i = blockIdx.x * 256 + threadIdx.x;
    float4 v = x[i];
    __half2 h0 = __floats2half2_rn(v.x, v.y);
    __half2 h1 = __floats2half2_rn(v.z, v.w);
    g_x16[i] = make_uint2(*(const uint32_t*)&h0, *(const uint32_t*)&h1);

    if (blockIdx.x < 64) {
        // 64*256 = 16384 threads over Bb*Tt/4 = 8192 words: 1 word for half of them
        int wi = blockIdx.x * 256 + threadIdx.x;
        int not_int = 0, not_flt = 0;
        if (wi < (Bb * Tt) / 4) {
            unsigned wv = mw[wi];
            if (wv > 1u) not_int = 1;
            if (wv != 0u && wv != 0x3F800000u) not_flt = 1;
        }
        if (__ballot_sync(0xffffffffu, not_int) && (threadIdx.x & 31) == 0)
            atomicOr(&g_flags[0], 1);
        if (__ballot_sync(0xffffffffu, not_flt) && (threadIdx.x & 31) == 0)
            atomicOr(&g_flags[1], 1);
    }
}

__device__ __forceinline__ float get_mask(const void* m, int idx, int mode) {
    if (mode == 1) return ((const int*)m)[idx] ? 1.0f : 0.0f;
    if (mode == 2) return ((const float*)m)[idx];
    return ((const unsigned char*)m)[idx] ? 1.0f : 0.0f;
}

__device__ __forceinline__ uint32_t smem_u32(const void* p) {
    uint32_t a;
    asm("{ .reg .u64 t; cvta.to.shared.u64 t, %1; cvt.u32.u64 %0, t; }" : "=r"(a) : "l"(p));
    return a;
}
__device__ __forceinline__ void cp16(uint32_t dst, const void* src) {
    asm volatile("cp.async.cg.shared.global [%0], [%1], 16;" :: "r"(dst), "l"(src));
}
#define CP_COMMIT() asm volatile("cp.async.commit_group;" ::: "memory")
#define CP_WAIT0()  asm volatile("cp.async.wait_group 0;" ::: "memory")

__device__ __forceinline__ void ldsm4(uint32_t r[4], uint32_t a) {
    asm volatile("ldmatrix.sync.aligned.m8n8.x4.shared.b16 {%0,%1,%2,%3}, [%4];"
                 : "=r"(r[0]), "=r"(r[1]), "=r"(r[2]), "=r"(r[3]) : "r"(a));
}
__device__ __forceinline__ void ldsm4t(uint32_t r[4], uint32_t a) {
    asm volatile("ldmatrix.sync.aligned.m8n8.x4.trans.shared.b16 {%0,%1,%2,%3}, [%4];"
                 : "=r"(r[0]), "=r"(r[1]), "=r"(r[2]), "=r"(r[3]) : "r"(a));
}
__device__ __forceinline__ void mma_f16(float d[4], const uint32_t a[4],
                                        uint32_t b0, uint32_t b1) {
    asm volatile(
        "mma.sync.aligned.m16n8k16.row.col.f32.f16.f16.f32 "
        "{%0,%1,%2,%3}, {%4,%5,%6,%7}, {%8,%9}, {%0,%1,%2,%3};"
        : "+f"(d[0]), "+f"(d[1]), "+f"(d[2]), "+f"(d[3])
        : "r"(a[0]), "r"(a[1]), "r"(a[2]), "r"(a[3]), "r"(b0), "r"(b1));
}

#define PAIR_BAR(id) asm volatile("bar.sync %0, 64;" :: "r"(id) : "memory")

// ---------------------------------------------------------------- main kernel
__global__ __launch_bounds__(256, 2)
void attn_mma(const void* __restrict__ mask, float* __restrict__ out) {
    extern __shared__ char sm[];
    const uint32_t sb = smem_u32(sm);

    const int tid  = threadIdx.x;
    const int w    = tid >> 5, lane = tid & 31;
    const int band = w >> 1;          // 0..3 : 32-row m-band
    const int half = w & 1;           // A: j-half (32); B: d-half (64)
    const int qrow = lane >> 2;       // 0..7
    const int qk   = lane & 3;        // 0..3
    const int arow0 = band * 32;

    const int b  = blockIdx.y;
    const int i0 = blockIdx.x * TM;
    const int mode = (!g_flags[0]) ? 1 : ((!g_flags[1]) ? 2 : 0);
    const char* gx = (const char*)g_x16;     // fp16 x, 256B per row

    // ldmatrix lane-address offsets (bytes, without ks / nb / buffer terms)
    const int l7 = lane & 7, l8 = (lane >> 3) & 1, l16 = (lane >> 4) & 1;
    const uint32_t offA_xi = (uint32_t)((arow0 + l7 + 8 * l8) * PX + l16 * 16);
    const uint32_t offB_A  = (uint32_t)((half * 32 + l7 + 8 * l16) * PX + l8 * 16);
    const uint32_t offA_P  = (uint32_t)((arow0 + l7 + 8 * l8) * PP + l16 * 16);
    const uint32_t offB_B  = (uint32_t)((l7 + 8 * l8) * PX + (half * 64 + 8 * l16) * 2);

    // ---- stage Xi (cp.async) + tile-0 Xj + masks ----
    {
        const int xr = tid >> 1;                          // 0..127
        const size_t srow = (size_t)(b * Tt + i0 + xr) * 256;
        #pragma unroll
        for (int i = 0; i < 8; i++) {
            const int ch = (tid & 1) + 2 * i;
            cp16(sb + SM_XI + xr * PX + ch * 16, gx + srow + ch * 16);
        }
        const int jr = tid >> 2;                          // 0..63
        const size_t jrow = (size_t)(b * Tt + jr) * 256;
        #pragma unroll
        for (int i = 0; i < 4; i++) {
            const int ch = (tid & 3) + 4 * i;
            cp16(sb + SM_XJ0 + jr * PX + ch * 16, gx + jrow + ch * 16);
        }
        CP_COMMIT();
    }
    if (tid < TM) ((float*)(sm + SM_MI))[tid] = get_mask(mask, b * Tt + i0 + tid, mode);
    if (tid < TN) ((float*)(sm + SM_MJ0))[tid] = get_mask(mask, b * Tt + tid, mode);

    float acc[2][8][4];
    #pragma unroll
    for (int mf = 0; mf < 2; mf++)
        #pragma unroll
        for (int nf = 0; nf < 8; nf++)
            #pragma unroll
            for (int c = 0; c < 4; c++) acc[mf][nf][c] = 0.0f;
    float rsum[2][2] = {{0.f, 0.f}, {0.f, 0.f}};

    for (int jt = 0; jt < NJT; ++jt) {
        const int j0 = jt * TN;
        const uint32_t xjb = sb + ((jt & 1) ? SM_XJ1 : SM_XJ0);
        const float* sMj = (const float*)(sm + ((jt & 1) ? SM_MJ1 : SM_MJ0));

        CP_WAIT0();
        __syncthreads();   // tile jt visible; all reads of the other buffer done

        // ---- issue cp.async for tile jt+1 into the other buffer ----
        if (jt + 1 < NJT) {
            const uint32_t dst = sb + (((jt + 1) & 1) ? SM_XJ1 : SM_XJ0);
            const int jr = tid >> 2;
            const size_t jrow = (size_t)(b * Tt + j0 + TN + jr) * 256;
            #pragma unroll
            for (int i = 0; i < 4; i++) {
                const int ch = (tid & 3) + 4 * i;
                cp16(dst + jr * PX + ch * 16, gx + jrow + ch * 16);
            }
            CP_COMMIT();
            if (tid < TN)
                ((float*)(sm + (((jt + 1) & 1) ? SM_MJ1 : SM_MJ0)))[tid] =
                    get_mask(mask, b * Tt + j0 + TN + tid, mode);
        }

        // ================= phase A: S(32x32 per warp) = Xi · Xjᵀ =================
        float s[2][4][4];
        #pragma unroll
        for (int mf = 0; mf < 2; mf++)
            #pragma unroll
            for (int nf = 0; nf < 4; nf++)
                #pragma unroll
                for (int c = 0; c < 4; c++) s[mf][nf][c] = 0.0f;

        #pragma unroll
        for (int ks = 0; ks < Dd / 16; ++ks) {
            uint32_t a[2][4];
            ldsm4(a[0], sb + SM_XI + offA_xi + ks * 32);
            ldsm4(a[1], sb + SM_XI + offA_xi + 16 * PX + ks * 32);
            #pragma unroll
            for (int nb = 0; nb < 2; nb++) {
                uint32_t bb[4];
                ldsm4(bb, xjb + offB_A + nb * 16 * PX + ks * 32);
                mma_f16(s[0][2 * nb],     a[0], bb[0], bb[1]);
                mma_f16(s[0][2 * nb + 1], a[0], bb[2], bb[3]);
                mma_f16(s[1][2 * nb],     a[1], bb[0], bb[1]);
                mma_f16(s[1][2 * nb + 1], a[1], bb[2], bb[3]);
            }
        }

        PAIR_BAR(1 + band);   // pair's phase B (prev tile) done reading P

        // ---- epilogue: P = exp(S + dist) * mj, rowsum, store P fp16 ----
        #pragma unroll
        for (int mf = 0; mf < 2; mf++) {
            const int rl0 = arow0 + mf * 16 + qrow;
            const int ig0 = i0 + rl0;
            #pragma unroll
            for (int nf = 0; nf < 4; nf++) {
                const int jl = half * 32 + nf * 8 + 2 * qk;
                const int jg = j0 + jl;
                const float mj0 = sMj[jl], mj1 = sMj[jl + 1];
                float p0 = __expf(s[mf][nf][0] + fminf((float)(ig0 - jg), 10.f)) * mj0;
                float p1 = __expf(s[mf][nf][1] + fminf((float)(ig0 - jg - 1), 10.f)) * mj1;
                float p2 = __expf(s[mf][nf][2] + fminf((float)(ig0 + 8 - jg), 10.f)) * mj0;
                float p3 = __expf(s[mf][nf][3] + fminf((float)(ig0 + 8 - jg - 1), 10.f)) * mj1;
                rsum[mf][0] += p0 + p1;
                rsum[mf][1] += p2 + p3;
                __half2 h01 = __floats2half2_rn(p0, p1);
                __half2 h23 = __floats2half2_rn(p2, p3);
                uint32_t* up = (uint32_t*)(sm + SM_P);
                const int ci = half * 16 + nf * 4 + qk;       // uint col index
                up[rl0 * 36 + ci]       = *(const uint32_t*)&h01;
                up[(rl0 + 8) * 36 + ci] = *(const uint32_t*)&h23;
            }
        }
        PAIR_BAR(1 + band);   // P visible to the pair

        // ================= phase B: O(32x64 per warp) += P · Xj =================
        #pragma unroll
        for (int ks = 0; ks < TN / 16; ++ks) {
            uint32_t a[2][4];
            ldsm4(a[0], sb + SM_P + offA_P + ks * 32);
            ldsm4(a[1], sb + SM_P + offA_P + 16 * PP + ks * 32);
            #pragma unroll
            for (int nb = 0; nb < 4; nb++) {
                uint32_t bb[4];
                ldsm4t(bb, xjb + offB_B + nb * 32 + ks * 16 * PX);
                mma_f16(acc[0][2 * nb],     a[0], bb[0], bb[1]);
                mma_f16(acc[0][2 * nb + 1], a[0], bb[2], bb[3]);
                mma_f16(acc[1][2 * nb],     a[1], bb[0], bb[1]);
                mma_f16(acc[1][2 * nb + 1], a[1], bb[2], bb[3]);
            }
        }
        // no end-of-loop barrier: the top barrier of jt+1 (after CP_WAIT0)
        // orders these reads before the cp.async that overwrites this buffer.
    }

    // ---- row-sum reduction + inverse ----
    float* sRP  = (float*)(sm + SM_RP);
    float* sInv = (float*)(sm + SM_INV);
    #pragma unroll
    for (int mf = 0; mf < 2; mf++)
        #pragma unroll
        for (int rh = 0; rh < 2; rh++) {
            float v = rsum[mf][rh];
            v += __shfl_xor_sync(0xffffffffu, v, 1);
            v += __shfl_xor_sync(0xffffffffu, v, 2);
            if (qk == 0) sRP[half * TM + arow0 + mf * 16 + rh * 8 + qrow] = v;
        }
    __syncthreads();
    if (tid < TM)
        sInv[tid] = ((float*)(sm + SM_MI))[tid] / (sRP[tid] + sRP[TM + tid] + EPSF);
    __syncthreads();

    // ---- write O ----
    #pragma unroll
    for (int mf = 0; mf < 2; mf++) {
        const int rl0 = arow0 + mf * 16 + qrow;
        const float inv0 = sInv[rl0], inv1 = sInv[rl0 + 8];
        float* o0 = out + ((size_t)b * Tt + i0 + rl0) * Dd;
        float* o1 = o0 + 8 * Dd;
        #pragma unroll
        for (int nf = 0; nf < 8; nf++) {
            const int cl = half * 64 + nf * 8 + 2 * qk;
            *(float2*)(o0 + cl) = make_float2(acc[mf][nf][0] * inv0, acc[mf][nf][1] * inv0);
            *(float2*)(o1 + cl) = make_float2(acc[mf][nf][2] * inv1, acc[mf][nf][3] * inv1);
        }
    }
}

extern "C" void kernel_launch(void* const* d_in, const int* in_sizes, int n_in,
                              void* d_out, int out_size) {
    const float* x   = (const float*)d_in[0];
    const void* mask = d_in[1];
    float* out       = (float*)d_out;

    cudaFuncSetAttribute(attn_mma, cudaFuncAttributeMaxDynamicSharedMemorySize, SMEM_BYTES);

    init_flags_kernel<<<1, 1>>>();
    cvt16_detect_kernel<<<(Bb * Tt * Dd / 4) / 256, 256>>>(
        (const float4*)x, (const unsigned int*)mask);
    dim3 grid(Tt / TM, Bb);
    attn_mma<<<grid, 256, SMEM_BYTES>>>(mask, out);
}